// round 7
// baseline (speedup 1.0000x reference)
#include <cuda_runtime.h>
#include <math.h>
#include <stdint.h>

// ---------------- problem constants ----------------
#define B_      1024
#define NTOK    54
#define WIN     49
#define NP      5
#define NH      12
#define HD      32
#define DIM     384
#define QKVD    1152
#define NWIN    64
#define WH      7
#define WW      7
#define SCALE   0.17677669529663687f
#define MTOK    (B_*NTOK)       // 55296
#define KDIM    384

// ---------------- scratch ----------------
__device__ float d_qkv[(size_t)MTOK * QKVD];
__device__ float d_att[(size_t)MTOK * DIM];      // tf32-rounded attention output
__device__ float d_xr[(size_t)MTOK * DIM];       // tf32-rounded x
__device__ float d_wq[QKVD * DIM];               // tf32-rounded qkv_w
__device__ float d_wp[DIM * DIM];                // tf32-rounded proj_w
__device__ float d_bm[NH * NWIN * 64 * 64];      // combined bias+mask, padded

__device__ __forceinline__ uint32_t f2tf32(float f) {
    uint32_t r;
    asm("cvt.rna.tf32.f32 %0, %1;" : "=r"(r) : "f"(f));
    return r;
}

// ---------------- prepass: round arrays to tf32 ----------------
__global__ void round_tf32(const float* __restrict__ in, float* __restrict__ out, int n4) {
    int i = blockIdx.x * blockDim.x + threadIdx.x;
    if (i >= n4) return;
    float4 v = reinterpret_cast<const float4*>(in)[i];
    v.x = __uint_as_float(f2tf32(v.x));
    v.y = __uint_as_float(f2tf32(v.y));
    v.z = __uint_as_float(f2tf32(v.z));
    v.w = __uint_as_float(f2tf32(v.w));
    reinterpret_cast<float4*>(out)[i] = v;
}

// ---------------- prepass: combined bias+mask table ----------------
__global__ void bm_kernel(const float* __restrict__ rpb, const float* __restrict__ mask) {
    int idx = blockIdx.x * blockDim.x + threadIdx.x;
    const int total = NH * NWIN * 64 * 64;
    if (idx >= total) return;
    int c  = idx & 63;
    int r  = (idx >> 6) & 63;
    int wv = (idx >> 12) & 63;
    int h  = idx >> 18;
    float v = 0.f;
    if (r < NTOK) {
        if (c < NTOK) {
            if (r >= NP && c >= NP) {
                int i = r - NP, j = c - NP;
                int ih = i / WW, iw = i % WW;
                int jh = j / WW, jw = j % WW;
                int rpi = (ih - jh + WH - 1) * (2 * WW - 1) + (iw - jw + WW - 1);
                v = rpb[rpi * NH + h] + mask[wv * WIN * WIN + i * WIN + j];
            }
        } else {
            v = -1e30f;
        }
    }
    d_bm[idx] = v;
}

// ================= tf32 mma.sync GEMM, BK=32, reg-level pipelining =======
// C[M,N] = A[M,384] @ W[N,384]^T + bias ; inputs pre-rounded to tf32
#define BM 128
#define BN 128
#define BK 32
#define PADK 36
#define TILEF   (BM * PADK)          // floats per matrix per buffer (4608)
#define ABYTES  (TILEF * 4)          // 18432
#define SMEM_GEMM (4 * ABYTES)       // 73728

__device__ __forceinline__ void cp16(uint32_t smem, const float* g) {
    asm volatile("cp.async.cg.shared.global [%0], [%1], 16;\n" :: "r"(smem), "l"(g));
}

__device__ __forceinline__ void mma_tf32(float* c,
    uint32_t a0, uint32_t a1, uint32_t a2, uint32_t a3,
    uint32_t b0, uint32_t b1)
{
    asm volatile(
        "mma.sync.aligned.m16n8k8.row.col.f32.tf32.tf32.f32 "
        "{%0,%1,%2,%3}, {%4,%5,%6,%7}, {%8,%9}, {%0,%1,%2,%3};\n"
        : "+f"(c[0]), "+f"(c[1]), "+f"(c[2]), "+f"(c[3])
        : "r"(a0), "r"(a1), "r"(a2), "r"(a3), "r"(b0), "r"(b1));
}

template<int N>
__device__ __forceinline__ void tgemm_body(
    const float* __restrict__ A, const float* __restrict__ W,
    const float* __restrict__ bias, float* __restrict__ C, int K)
{
    extern __shared__ __align__(16) float smem[];
    float* As = smem;                   // [2][TILEF]
    float* Bs = smem + 2 * TILEF;       // [2][TILEF]

    const int tid  = threadIdx.x;
    const int warp = tid >> 5, lane = tid & 31;
    const int g    = lane >> 2, tg = lane & 3;
    const int wm   = warp & 1;
    const int wn   = warp >> 1;
    const int m0   = blockIdx.y * BM;
    const int n0   = blockIdx.x * BN;

    // producer: row = tid/2 (0..127), kq = (tid&1)*16 ; 4 float4 per matrix
    const int lr = tid >> 1;
    const int kq = (tid & 1) * 16;
    const float* Ag = A + (size_t)(m0 + lr) * K + kq;
    const float* Wg = W + (size_t)(n0 + lr) * K + kq;

    uint32_t sAb = (uint32_t)__cvta_generic_to_shared(As);
    uint32_t sBb = (uint32_t)__cvta_generic_to_shared(Bs);
    const uint32_t sAo = sAb + (lr * PADK + kq) * 4;
    const uint32_t sBo = sBb + (lr * PADK + kq) * 4;

    float acc[4][4][4];
    #pragma unroll
    for (int i = 0; i < 4; i++)
        #pragma unroll
        for (int j = 0; j < 4; j++)
            #pragma unroll
            for (int c = 0; c < 4; c++) acc[i][j][c] = 0.f;

    const int nt = K / BK;       // 12

    // prologue: tile 0 -> buffer 0
    #pragma unroll
    for (int j = 0; j < 4; j++) {
        cp16(sAo + j * 16, Ag + j * 4);
        cp16(sBo + j * 16, Wg + j * 4);
    }
    asm volatile("cp.async.commit_group;\n");

    uint32_t af[2][4][4], bf[2][4][2];

    for (int t = 0; t < nt; t++) {
        asm volatile("cp.async.wait_group 0;\n");
        __syncthreads();
        const int buf = t & 1;
        if (t + 1 < nt) {
            const float* ap = Ag + (size_t)(t + 1) * BK;
            const float* wp = Wg + (size_t)(t + 1) * BK;
            const uint32_t bo = (buf ^ 1) * ABYTES;
            #pragma unroll
            for (int j = 0; j < 4; j++) {
                cp16(sAo + bo + j * 16, ap + j * 4);
                cp16(sBo + bo + j * 16, wp + j * 4);
            }
            asm volatile("cp.async.commit_group;\n");
        }

        const float* __restrict__ Asb = As + buf * TILEF;
        const float* __restrict__ Bsb = Bs + buf * TILEF;

        // load fragments for s = 0
        {
            const int kb = 0;
            #pragma unroll
            for (int i = 0; i < 4; i++) {
                const int rb = wm * 64 + i * 16;
                af[0][i][0] = __float_as_uint(Asb[(rb + g)     * PADK + kb + tg]);
                af[0][i][1] = __float_as_uint(Asb[(rb + g + 8) * PADK + kb + tg]);
                af[0][i][2] = __float_as_uint(Asb[(rb + g)     * PADK + kb + tg + 4]);
                af[0][i][3] = __float_as_uint(Asb[(rb + g + 8) * PADK + kb + tg + 4]);
            }
            #pragma unroll
            for (int j = 0; j < 4; j++) {
                const int cb = wn * 32 + j * 8;
                bf[0][j][0] = __float_as_uint(Bsb[(cb + g) * PADK + kb + tg]);
                bf[0][j][1] = __float_as_uint(Bsb[(cb + g) * PADK + kb + tg + 4]);
            }
        }

        #pragma unroll
        for (int s = 0; s < 4; s++) {
            const int cur = s & 1;
            // prefetch fragments for s+1 while MMAs of s issue
            if (s < 3) {
                const int nxt = cur ^ 1;
                const int kb = (s + 1) * 8;
                #pragma unroll
                for (int i = 0; i < 4; i++) {
                    const int rb = wm * 64 + i * 16;
                    af[nxt][i][0] = __float_as_uint(Asb[(rb + g)     * PADK + kb + tg]);
                    af[nxt][i][1] = __float_as_uint(Asb[(rb + g + 8) * PADK + kb + tg]);
                    af[nxt][i][2] = __float_as_uint(Asb[(rb + g)     * PADK + kb + tg + 4]);
                    af[nxt][i][3] = __float_as_uint(Asb[(rb + g + 8) * PADK + kb + tg + 4]);
                }
                #pragma unroll
                for (int j = 0; j < 4; j++) {
                    const int cb = wn * 32 + j * 8;
                    bf[nxt][j][0] = __float_as_uint(Bsb[(cb + g) * PADK + kb + tg]);
                    bf[nxt][j][1] = __float_as_uint(Bsb[(cb + g) * PADK + kb + tg + 4]);
                }
            }
            #pragma unroll
            for (int i = 0; i < 4; i++)
                #pragma unroll
                for (int j = 0; j < 4; j++)
                    mma_tf32(acc[i][j],
                             af[cur][i][0], af[cur][i][1], af[cur][i][2], af[cur][i][3],
                             bf[cur][j][0], bf[cur][j][1]);
        }
        __syncthreads();
    }

    // epilogue: add bias, store
    #pragma unroll
    for (int i = 0; i < 4; i++) {
        const int rb = m0 + wm * 64 + i * 16 + g;
        #pragma unroll
        for (int j = 0; j < 4; j++) {
            const int cb = n0 + wn * 32 + j * 8 + 2 * tg;
            const float b0v = bias[cb], b1v = bias[cb + 1];
            float2 v0, v1;
            v0.x = acc[i][j][0] + b0v;  v0.y = acc[i][j][1] + b1v;
            v1.x = acc[i][j][2] + b0v;  v1.y = acc[i][j][3] + b1v;
            *reinterpret_cast<float2*>(&C[(size_t)rb * N + cb])       = v0;
            *reinterpret_cast<float2*>(&C[(size_t)(rb + 8) * N + cb]) = v1;
        }
    }
}

__global__ __launch_bounds__(256, 2) void k_qkv(const float* __restrict__ b)
{
    tgemm_body<QKVD>(d_xr, d_wq, b, d_qkv, KDIM);
}

__global__ __launch_bounds__(256, 2) void k_proj(const float* __restrict__ b,
                                                 float* __restrict__ out)
{
    tgemm_body<DIM>(d_att, d_wp, b, out, KDIM);
}

// ================= tensor-core attention: one block (128 thr) per (b,h) ==
#define SQH 0
#define SKH 2304
#define SVT 4608
#define SQL 6784
#define SKL (6784 + 2304)
#define SPP 6784
#define SMTOT 11392

__global__ __launch_bounds__(128) void attn_tc()
{
    __shared__ uint32_t sm[SMTOT];

    const int b = blockIdx.x / NH;
    const int h = blockIdx.x % NH;
    const int tid = threadIdx.x;

    const float* base = d_qkv + (size_t)b * NTOK * QKVD + h * HD;

    for (int idx = tid; idx < 64 * 32; idx += 128) {
        const int r = idx >> 5, d = idx & 31;
        float qv = 0.f, kv = 0.f, vv = 0.f;
        if (r < NTOK) {
            qv = base[r * QKVD + d] * SCALE;
            kv = base[r * QKVD + DIM + d];
            vv = base[r * QKVD + 2 * DIM + d];
        }
        const uint32_t qhi = f2tf32(qv);
        const uint32_t khi = f2tf32(kv);
        const float qlo = qv - __uint_as_float(qhi);
        const float klo = kv - __uint_as_float(khi);
        sm[SQH + r * 36 + d] = qhi;
        sm[SKH + r * 36 + d] = khi;
        sm[SQL + r * 36 + d] = f2tf32(qlo);
        sm[SKL + r * 36 + d] = f2tf32(klo);
        sm[SVT + d * 68 + r] = f2tf32(vv);
    }
    __syncthreads();

    const int w = tid >> 5, lane = tid & 31;
    const int g = lane >> 2, tg = lane & 3;
    const int r0 = w * 16 + g;

    float s[8][4];
    #pragma unroll
    for (int j = 0; j < 8; j++)
        #pragma unroll
        for (int c = 0; c < 4; c++) s[j][c] = 0.f;

    #pragma unroll
    for (int kk = 0; kk < 4; kk++) {
        const int ko = kk * 8;
        const uint32_t a0 = sm[SQH + r0 * 36 + ko + tg];
        const uint32_t a1 = sm[SQH + (r0 + 8) * 36 + ko + tg];
        const uint32_t a2 = sm[SQH + r0 * 36 + ko + tg + 4];
        const uint32_t a3 = sm[SQH + (r0 + 8) * 36 + ko + tg + 4];
        const uint32_t l0 = sm[SQL + r0 * 36 + ko + tg];
        const uint32_t l1 = sm[SQL + (r0 + 8) * 36 + ko + tg];
        const uint32_t l2 = sm[SQL + r0 * 36 + ko + tg + 4];
        const uint32_t l3 = sm[SQL + (r0 + 8) * 36 + ko + tg + 4];
        #pragma unroll
        for (int j = 0; j < 8; j++) {
            const int kr = j * 8 + g;
            const uint32_t b0 = sm[SKH + kr * 36 + ko + tg];
            const uint32_t b1 = sm[SKH + kr * 36 + ko + tg + 4];
            const uint32_t c0 = sm[SKL + kr * 36 + ko + tg];
            const uint32_t c1 = sm[SKL + kr * 36 + ko + tg + 4];
            mma_tf32(s[j], a0, a1, a2, a3, b0, b1);
            mma_tf32(s[j], l0, l1, l2, l3, b0, b1);
            mma_tf32(s[j], a0, a1, a2, a3, c0, c1);
        }
    }

    const float* bmp = d_bm + ((size_t)(h * NWIN + (b & (NWIN - 1)))) * 64 * 64;
    #pragma unroll
    for (int j = 0; j < 8; j++) {
        const float2 t0 = *reinterpret_cast<const float2*>(&bmp[r0 * 64 + j * 8 + 2 * tg]);
        const float2 t1 = *reinterpret_cast<const float2*>(&bmp[(r0 + 8) * 64 + j * 8 + 2 * tg]);
        s[j][0] += t0.x;  s[j][1] += t0.y;
        s[j][2] += t1.x;  s[j][3] += t1.y;
    }

    float m0 = -1e30f, m1 = -1e30f;
    #pragma unroll
    for (int j = 0; j < 8; j++) {
        m0 = fmaxf(m0, fmaxf(s[j][0], s[j][1]));
        m1 = fmaxf(m1, fmaxf(s[j][2], s[j][3]));
    }
    m0 = fmaxf(m0, __shfl_xor_sync(0xffffffffu, m0, 1));
    m0 = fmaxf(m0, __shfl_xor_sync(0xffffffffu, m0, 2));
    m1 = fmaxf(m1, __shfl_xor_sync(0xffffffffu, m1, 1));
    m1 = fmaxf(m1, __shfl_xor_sync(0xffffffffu, m1, 2));

    float sum0 = 0.f, sum1 = 0.f;
    #pragma unroll
    for (int j = 0; j < 8; j++) {
        s[j][0] = __expf(s[j][0] - m0);
        s[j][1] = __expf(s[j][1] - m0);
        s[j][2] = __expf(s[j][2] - m1);
        s[j][3] = __expf(s[j][3] - m1);
        sum0 += s[j][0] + s[j][1];
        sum1 += s[j][2] + s[j][3];
    }
    sum0 += __shfl_xor_sync(0xffffffffu, sum0, 1);
    sum0 += __shfl_xor_sync(0xffffffffu, sum0, 2);
    sum1 += __shfl_xor_sync(0xffffffffu, sum1, 1);
    sum1 += __shfl_xor_sync(0xffffffffu, sum1, 2);
    const float inv0 = 1.f / sum0;
    const float inv1 = 1.f / sum1;

    __syncthreads();   // QL/KL reads done before PP overwrites

    #pragma unroll
    for (int j = 0; j < 8; j++) {
        uint2 p0, p1;
        p0.x = f2tf32(s[j][0] * inv0);  p0.y = f2tf32(s[j][1] * inv0);
        p1.x = f2tf32(s[j][2] * inv1);  p1.y = f2tf32(s[j][3] * inv1);
        *reinterpret_cast<uint2*>(&sm[SPP + r0 * 68 + j * 8 + 2 * tg])       = p0;
        *reinterpret_cast<uint2*>(&sm[SPP + (r0 + 8) * 68 + j * 8 + 2 * tg]) = p1;
    }
    __syncwarp();

    float o[4][4];
    #pragma unroll
    for (int n = 0; n < 4; n++)
        #pragma unroll
        for (int c = 0; c < 4; c++) o[n][c] = 0.f;

    #pragma unroll
    for (int kk = 0; kk < 8; kk++) {
        const int ko = kk * 8;
        const uint32_t a0 = sm[SPP + r0 * 68 + ko + tg];
        const uint32_t a1 = sm[SPP + (r0 + 8) * 68 + ko + tg];
        const uint32_t a2 = sm[SPP + r0 * 68 + ko + tg + 4];
        const uint32_t a3 = sm[SPP + (r0 + 8) * 68 + ko + tg + 4];
        #pragma unroll
        for (int n = 0; n < 4; n++) {
            const int vr = n * 8 + g;
            const uint32_t b0 = sm[SVT + vr * 68 + ko + tg];
            const uint32_t b1 = sm[SVT + vr * 68 + ko + tg + 4];
            mma_tf32(o[n], a0, a1, a2, a3, b0, b1);
        }
    }

    if (r0 < NTOK) {
        float* op = d_att + ((size_t)b * NTOK + r0) * DIM + h * HD;
        #pragma unroll
        for (int n = 0; n < 4; n++) {
            float2 v;
            v.x = __uint_as_float(f2tf32(o[n][0]));
            v.y = __uint_as_float(f2tf32(o[n][1]));
            *reinterpret_cast<float2*>(&op[n * 8 + 2 * tg]) = v;
        }
    }
    if (r0 + 8 < NTOK) {
        float* op = d_att + ((size_t)b * NTOK + r0 + 8) * DIM + h * HD;
        #pragma unroll
        for (int n = 0; n < 4; n++) {
            float2 v;
            v.x = __uint_as_float(f2tf32(o[n][2]));
            v.y = __uint_as_float(f2tf32(o[n][3]));
            *reinterpret_cast<float2*>(&op[n * 8 + 2 * tg]) = v;
        }
    }
}

// ---------------- launch ----------------
extern "C" void kernel_launch(void* const* d_in, const int* in_sizes, int n_in,
                              void* d_out, int out_size)
{
    const float* x      = (const float*)d_in[0];
    const float* mask   = (const float*)d_in[1];
    const float* qkv_w  = (const float*)d_in[2];
    const float* qkv_b  = (const float*)d_in[3];
    const float* proj_w = (const float*)d_in[4];
    const float* proj_b = (const float*)d_in[5];
    const float* rpb    = (const float*)d_in[6];
    float* out          = (float*)d_out;

    cudaFuncSetAttribute(k_qkv,  cudaFuncAttributeMaxDynamicSharedMemorySize, SMEM_GEMM);
    cudaFuncSetAttribute(k_proj, cudaFuncAttributeMaxDynamicSharedMemorySize, SMEM_GEMM);

    float *xr, *wq, *wp;
    cudaGetSymbolAddress((void**)&xr, d_xr);
    cudaGetSymbolAddress((void**)&wq, d_wq);
    cudaGetSymbolAddress((void**)&wp, d_wp);

    {
        int n4 = (MTOK * DIM) / 4;
        round_tf32<<<(n4 + 255) / 256, 256>>>(x, xr, n4);
        n4 = (QKVD * DIM) / 4;
        round_tf32<<<(n4 + 255) / 256, 256>>>(qkv_w, wq, n4);
        n4 = (DIM * DIM) / 4;
        round_tf32<<<(n4 + 255) / 256, 256>>>(proj_w, wp, n4);
        const int total = NH * NWIN * 64 * 64;
        bm_kernel<<<(total + 255) / 256, 256>>>(rpb, mask);
    }

    {   // QKV: (55296 x 384) @ (1152 x 384)^T
        dim3 grid(QKVD / BN, MTOK / BM);
        k_qkv<<<grid, 256, SMEM_GEMM>>>(qkv_b);
    }

    attn_tc<<<B_ * NH, 128>>>();

    {   // proj: (55296 x 384) @ (384 x 384)^T
        dim3 grid(DIM / BN, MTOK / BM);
        k_proj<<<grid, 256, SMEM_GEMM>>>(proj_b, out);
    }
}